// round 10
// baseline (speedup 1.0000x reference)
#include <cuda_runtime.h>
#include <cuda_fp16.h>
#include <cstdint>

// Sparse block attention: B=1, H=16, S=8192, D=64, BS=64, NB=128
// Pattern per q-block i: {0} U [max(0,i-7), i]; causal inside diagonal block.
// HMMA; 128 q-rows per 4-warp CTA (2 m-tiles/warp), fixed-max softmax.
// R10: cp.async fp32 staging pipeline (loads hidden behind compute) +
//      ex2.approx.f16x2 fused exp/convert (half the MUFU traffic).
#define HEADS  16
#define SEQ    8192
#define DIM    64
#define BSZ    64
#define NBLK   128
#define LOCALW 8
#define LDH    72        // half stride: 144B rows -> conflict-free ldmatrix
#define LDS4   68        // staging float stride: 272B rows (17 quads, odd) -> conflict-free

// dynamic smem layout (bytes)
#define QS_OFF   0                 // 128 x LDH halves = 18432
#define KT_OFF   18432             // 64 x LDH halves  = 9216
#define VT_OFF   27648             // 9216
#define KST_OFF  36864             // 64 x 272B = 17408 (fp32 staging)
#define VST_OFF  54272             // 17408
#define SMEM_TOTAL 71680

__device__ __forceinline__ uint32_t pkh2(float a, float b) {
    __half2 h = __floats2half2_rn(a, b);
    return *reinterpret_cast<uint32_t*>(&h);
}
__device__ __forceinline__ uint32_t ex2h2(uint32_t x) {
    uint32_t y; asm("ex2.approx.f16x2 %0, %1;" : "=r"(y) : "r"(x)); return y;
}
__device__ __forceinline__ float2 h22f2(uint32_t x) {
    __half2 h = *reinterpret_cast<__half2*>(&x);
    return __half22float2(h);
}
__device__ __forceinline__ void cpa16(uint32_t dst, const float* src) {
    asm volatile("cp.async.cg.shared.global [%0], [%1], 16;" :: "r"(dst), "l"(src));
}
__device__ __forceinline__ void ldsm_x4(uint32_t& r0, uint32_t& r1, uint32_t& r2, uint32_t& r3, uint32_t a) {
    asm volatile("ldmatrix.sync.aligned.m8n8.x4.shared.b16 {%0,%1,%2,%3}, [%4];"
                 : "=r"(r0), "=r"(r1), "=r"(r2), "=r"(r3) : "r"(a));
}
__device__ __forceinline__ void ldsm_x4t(uint32_t& r0, uint32_t& r1, uint32_t& r2, uint32_t& r3, uint32_t a) {
    asm volatile("ldmatrix.sync.aligned.m8n8.x4.trans.shared.b16 {%0,%1,%2,%3}, [%4];"
                 : "=r"(r0), "=r"(r1), "=r"(r2), "=r"(r3) : "r"(a));
}
__device__ __forceinline__ void mma16816(float* c, uint32_t a0, uint32_t a1, uint32_t a2, uint32_t a3,
                                         uint32_t b0, uint32_t b1) {
    asm volatile("mma.sync.aligned.m16n8k16.row.col.f32.f16.f16.f32 "
                 "{%0,%1,%2,%3}, {%4,%5,%6,%7}, {%8,%9}, {%0,%1,%2,%3};"
                 : "+f"(c[0]), "+f"(c[1]), "+f"(c[2]), "+f"(c[3])
                 : "r"(a0), "r"(a1), "r"(a2), "r"(a3), "r"(b0), "r"(b1));
}

__global__ __launch_bounds__(128, 2)
void sparse_attn_hmma7(const float* __restrict__ q,
                       const float* __restrict__ k,
                       const float* __restrict__ v,
                       float* __restrict__ out)
{
    extern __shared__ __align__(16) char dsm[];
    __half* Qs = (__half*)(dsm + QS_OFF);
    __half* Kt = (__half*)(dsm + KT_OFF);
    __half* Vt = (__half*)(dsm + VT_OFF);

    const int bx   = blockIdx.x;
    const int h    = blockIdx.y;
    const int tid  = threadIdx.x;
    const int lane = tid & 31;
    const int w    = tid >> 5;

    const int my_ib = 2 * bx + (w >> 1);
    const int ibp   = 2 * bx + 1;
    const int nnz   = (ibp <= 8) ? (ibp + 1) : 10;

    const uint32_t smb  = (uint32_t)__cvta_generic_to_shared(dsm);
    const uint32_t kstb = smb + KST_OFF;
    const uint32_t vstb = smb + VST_OFF;

    const float* kh = k + (size_t)h * SEQ * DIM;
    const float* vh = v + (size_t)h * SEQ * DIM;

    // per-thread staging coords: 16 chunks of 16B per tile (8 rows-groups x ...)
    // chunk i (0..15): row = (tid>>4)+8*(i>>1)... use i = tid + 128*j mapping:
    //   idx j in [0,8): linear chunk id = tid + 128*j; row = id>>4, ch = id&15
    const int strow = tid >> 4;            // +16 per j... (id>>4 = tid>>4 + 8j? no)
    // note: id = tid + 128*j -> id>>4 = (tid>>4) + 8*j ; ch = tid&15
    const int stch  = tid & 15;

    // ---- prologue: issue cp.async for jb=0, load Q meanwhile ----
    {
        #pragma unroll
        for (int j = 0; j < 8; ++j) {
            int row = strow + 8 * j;
            cpa16(kstb + row * 272 + stch * 16, kh + row * DIM + stch * 4);
            cpa16(vstb + row * 272 + stch * 16, vh + row * DIM + stch * 4);
        }
        asm volatile("cp.async.commit_group;");
    }
    {
        const float qscale = 0.125f * 1.4426950408889634f;
        const float* qg = q + ((size_t)h * SEQ + (size_t)bx * 128) * DIM;
        #pragma unroll
        for (int j = 0; j < 16; ++j) {
            int i   = tid + 128 * j;
            int row = i >> 4;
            int c4  = (i & 15) << 2;
            float4 val = *(const float4*)(qg + row * DIM + c4);
            uint2 u;
            u.x = pkh2(val.x * qscale, val.y * qscale);
            u.y = pkh2(val.z * qscale, val.w * qscale);
            *(uint2*)&Qs[row * LDH + c4] = u;
        }
    }
    asm volatile("cp.async.wait_group 0;");
    __syncthreads();

    // ---- convert staging -> fp16 tiles (jb=0) ----
    {
        #pragma unroll
        for (int j = 0; j < 8; ++j) {
            int i   = tid + 128 * j;
            int row = i >> 4;
            int c4  = (i & 15) << 2;
            float4 kv = *(const float4*)(dsm + KST_OFF + row * 272 + c4 * 4);
            uint2 uk; uk.x = pkh2(kv.x, kv.y); uk.y = pkh2(kv.z, kv.w);
            *(uint2*)&Kt[row * LDH + c4] = uk;
            float4 vv = *(const float4*)(dsm + VST_OFF + row * 272 + c4 * 4);
            uint2 uv; uv.x = pkh2(vv.x, vv.y); uv.y = pkh2(vv.z, vv.w);
            *(uint2*)&Vt[row * LDH + c4] = uv;
        }
    }
    __syncthreads();

    // ---- issue cp.async for jb(1) ----
    if (nnz > 1) {
        const int j1 = (ibp <= 8) ? 1 : (ibp - 8);
        const float* kg = kh + (size_t)j1 * BSZ * DIM;
        const float* vg = vh + (size_t)j1 * BSZ * DIM;
        #pragma unroll
        for (int j = 0; j < 8; ++j) {
            int row = strow + 8 * j;
            cpa16(kstb + row * 272 + stch * 16, kg + row * DIM + stch * 4);
            cpa16(vstb + row * 272 + stch * 16, vg + row * DIM + stch * 4);
        }
        asm volatile("cp.async.commit_group;");
    }

    const uint32_t qsb = smb + QS_OFF;
    const uint32_t ksb = smb + KT_OFF;
    const uint32_t vsb = smb + VT_OFF;

    // ---- persistent Q A-fragments ----
    uint32_t aq[2][4][4];
    {
        int r   = lane & 15;
        int chi = (lane >> 4) * 8;
        #pragma unroll
        for (int mi = 0; mi < 2; ++mi) {
            uint32_t base = qsb + (((32 * w + 16 * mi + r) * LDH + chi) << 1);
            #pragma unroll
            for (int c = 0; c < 4; ++c)
                ldsm_x4(aq[mi][c][0], aq[mi][c][1], aq[mi][c][2], aq[mi][c][3],
                        base + ((16 * c) << 1));
        }
    }

    const int g8 = lane >> 3;
    const int r8 = lane & 7;

    float O[2][8][4];
    float lsum[2][2];
    #pragma unroll
    for (int mi = 0; mi < 2; ++mi) {
        lsum[mi][0] = 0.f; lsum[mi][1] = 0.f;
        #pragma unroll
        for (int j = 0; j < 8; ++j)
            #pragma unroll
            for (int e = 0; e < 4; ++e) O[mi][j][e] = 0.f;
    }

    const int rbase0 = 32 * (w & 1);
    const int c0loc  = 2 * (lane & 3);
    const int rq     = lane >> 2;

    for (int t = 0; t < nnz; ++t) {
        const int jb = (ibp <= 8) ? t : ((t == 0) ? 0 : (ibp - 9 + t));
        const bool active = (jb == 0) || (jb >= my_ib - (LOCALW - 1) && jb <= my_ib);

        if (active) {
            uint32_t pa[2][4][4];

            #pragma unroll
            for (int mi = 0; mi < 2; ++mi) {
                float S[8][4];
                #pragma unroll
                for (int j = 0; j < 8; ++j)
                    #pragma unroll
                    for (int e = 0; e < 4; ++e) S[j][e] = 0.f;

                #pragma unroll
                for (int nj = 0; nj < 8; ++nj) {
                    uint32_t a0 = ksb + (((8 * nj + r8) * LDH + 8 * (g8 & 1) + 16 * (g8 >> 1)) << 1);
                    uint32_t b0, b1, b2, b3, b4, b5, b6, b7;
                    ldsm_x4(b0, b1, b2, b3, a0);
                    ldsm_x4(b4, b5, b6, b7, a0 + 64);
                    mma16816(S[nj], aq[mi][0][0], aq[mi][0][1], aq[mi][0][2], aq[mi][0][3], b0, b1);
                    mma16816(S[nj], aq[mi][1][0], aq[mi][1][1], aq[mi][1][2], aq[mi][1][3], b2, b3);
                    mma16816(S[nj], aq[mi][2][0], aq[mi][2][1], aq[mi][2][2], aq[mi][2][3], b4, b5);
                    mma16816(S[nj], aq[mi][3][0], aq[mi][3][1], aq[mi][3][2], aq[mi][3][3], b6, b7);
                }

                if (jb == my_ib) {
                    int r0 = rbase0 + 16 * mi + rq;
                    #pragma unroll
                    for (int nj = 0; nj < 8; ++nj) {
                        int cn = 8 * nj + c0loc;
                        if (cn     > r0)     S[nj][0] = -1e30f;
                        if (cn + 1 > r0)     S[nj][1] = -1e30f;
                        if (cn     > r0 + 8) S[nj][2] = -1e30f;
                        if (cn + 1 > r0 + 8) S[nj][3] = -1e30f;
                    }
                }

                // fused exp2 + f16 pack (ex2.approx.f16x2); row sums from the
                // same f16 p values the PV MMA will consume
                float ps0 = 0.f, ps1 = 0.f;
                #pragma unroll
                for (int c = 0; c < 4; ++c) {
                    uint32_t p00 = ex2h2(pkh2(S[2 * c][0],     S[2 * c][1]));
                    uint32_t p01 = ex2h2(pkh2(S[2 * c][2],     S[2 * c][3]));
                    uint32_t p10 = ex2h2(pkh2(S[2 * c + 1][0], S[2 * c + 1][1]));
                    uint32_t p11 = ex2h2(pkh2(S[2 * c + 1][2], S[2 * c + 1][3]));
                    pa[mi][c][0] = p00;
                    pa[mi][c][1] = p01;
                    pa[mi][c][2] = p10;
                    pa[mi][c][3] = p11;
                    float2 f;
                    f = h22f2(p00); ps0 += f.x + f.y;
                    f = h22f2(p10); ps0 += f.x + f.y;
                    f = h22f2(p01); ps1 += f.x + f.y;
                    f = h22f2(p11); ps1 += f.x + f.y;
                }
                lsum[mi][0] += ps0;
                lsum[mi][1] += ps1;
            }

            // ---- O += P @ V : V frags loaded once per nj, shared across mi ----
            #pragma unroll
            for (int nj = 0; nj < 8; ++nj) {
                uint32_t v0 = vsb + (((8 * g8 + r8) * LDH + 8 * nj) << 1);
                uint32_t v1 = vsb + (((32 + 8 * g8 + r8) * LDH + 8 * nj) << 1);
                uint32_t c0, c1, c2, c3, c4, c5, c6, c7;
                ldsm_x4t(c0, c1, c2, c3, v0);
                ldsm_x4t(c4, c5, c6, c7, v1);
                #pragma unroll
                for (int mi = 0; mi < 2; ++mi) {
                    mma16816(O[mi][nj], pa[mi][0][0], pa[mi][0][1], pa[mi][0][2], pa[mi][0][3], c0, c1);
                    mma16816(O[mi][nj], pa[mi][1][0], pa[mi][1][1], pa[mi][1][2], pa[mi][1][3], c2, c3);
                    mma16816(O[mi][nj], pa[mi][2][0], pa[mi][2][1], pa[mi][2][2], pa[mi][2][3], c4, c5);
                    mma16816(O[mi][nj], pa[mi][3][0], pa[mi][3][1], pa[mi][3][2], pa[mi][3][3], c6, c7);
                }
            }
        }
        __syncthreads();   // all warps done reading Kt/Vt

        // ---- pipeline tail: land t+1 into tiles, issue t+2 ----
        if (t + 1 < nnz) {
            asm volatile("cp.async.wait_group 0;");
            __syncthreads();           // staging(t+1) visible to all
            #pragma unroll
            for (int j = 0; j < 8; ++j) {
                int i   = tid + 128 * j;
                int row = i >> 4;
                int c4  = (i & 15) << 2;
                float4 kv = *(const float4*)(dsm + KST_OFF + row * 272 + c4 * 4);
                uint2 uk; uk.x = pkh2(kv.x, kv.y); uk.y = pkh2(kv.z, kv.w);
                *(uint2*)&Kt[row * LDH + c4] = uk;
                float4 vv = *(const float4*)(dsm + VST_OFF + row * 272 + c4 * 4);
                uint2 uv; uv.x = pkh2(vv.x, vv.y); uv.y = pkh2(vv.z, vv.w);
                *(uint2*)&Vt[row * LDH + c4] = uv;
            }
            __syncthreads();           // converts done; staging free
            if (t + 2 < nnz) {
                const int j2 = (ibp <= 8) ? (t + 2) : (ibp - 7 + t);
                const float* kg = kh + (size_t)j2 * BSZ * DIM;
                const float* vg = vh + (size_t)j2 * BSZ * DIM;
                #pragma unroll
                for (int j = 0; j < 8; ++j) {
                    int row = strow + 8 * j;
                    cpa16(kstb + row * 272 + stch * 16, kg + row * DIM + stch * 4);
                    cpa16(vstb + row * 272 + stch * 16, vg + row * DIM + stch * 4);
                }
                asm volatile("cp.async.commit_group;");
            }
        }
    }

    // ---- epilogue: normalize + store ----
    float* og = out + ((size_t)h * SEQ + (size_t)bx * 128) * DIM;
    #pragma unroll
    for (int mi = 0; mi < 2; ++mi) {
        float s0 = lsum[mi][0] + __shfl_xor_sync(0xffffffffu, lsum[mi][0], 1);
        s0 += __shfl_xor_sync(0xffffffffu, s0, 2);
        float s1 = lsum[mi][1] + __shfl_xor_sync(0xffffffffu, lsum[mi][1], 1);
        s1 += __shfl_xor_sync(0xffffffffu, s1, 2);
        float inv0 = 1.0f / s0;
        float inv1 = 1.0f / s1;
        int gr = 32 * w + 16 * mi + rq;
        #pragma unroll
        for (int nj = 0; nj < 8; ++nj) {
            int cn = 8 * nj + c0loc;
            float2 o0 = make_float2(O[mi][nj][0] * inv0, O[mi][nj][1] * inv0);
            float2 o1 = make_float2(O[mi][nj][2] * inv1, O[mi][nj][3] * inv1);
            *(float2*)(og + (size_t)gr * DIM + cn)       = o0;
            *(float2*)(og + (size_t)(gr + 8) * DIM + cn) = o1;
        }
    }
}

extern "C" void kernel_launch(void* const* d_in, const int* in_sizes, int n_in,
                              void* d_out, int out_size)
{
    const float* q = (const float*)d_in[0];
    const float* k = (const float*)d_in[1];
    const float* v = (const float*)d_in[2];
    float* out = (float*)d_out;

    cudaFuncSetAttribute(sparse_attn_hmma7,
                         cudaFuncAttributeMaxDynamicSharedMemorySize, SMEM_TOTAL);

    dim3 grid(NBLK / 2, HEADS);
    sparse_attn_hmma7<<<grid, 128, SMEM_TOTAL>>>(q, k, v, out);
}

// round 11
// speedup vs baseline: 1.1428x; 1.1428x over previous
#include <cuda_runtime.h>
#include <cuda_fp16.h>
#include <cstdint>

// Sparse block attention: B=1, H=16, S=8192, D=64, BS=64, NB=128
// Pattern per q-block i: {0} U [max(0,i-7), i]; causal inside diagonal block.
// R11: 256-thread CTA (8 warps x 16 rows = 128 q-rows = 2 q-blocks), fixed-max
// softmax with IMMEDIATE per-nj exp (S live set = 4 regs) -> ~110 regs ->
// 2 CTAs/SM = 16 warps/SM (2x occupancy vs R8).
#define HEADS  16
#define SEQ    8192
#define DIM    64
#define BSZ    64
#define NBLK   128
#define LOCALW 8
#define LDH    72   // half stride: 144B rows -> conflict-free ldmatrix

__device__ __forceinline__ float ex2f(float x) {
    float y; asm("ex2.approx.ftz.f32 %0, %1;" : "=f"(y) : "f"(x)); return y;
}
__device__ __forceinline__ uint32_t pkh2(float a, float b) {
    __half2 h = __floats2half2_rn(a, b);
    return *reinterpret_cast<uint32_t*>(&h);
}
__device__ __forceinline__ void ldsm_x4(uint32_t& r0, uint32_t& r1, uint32_t& r2, uint32_t& r3, uint32_t a) {
    asm volatile("ldmatrix.sync.aligned.m8n8.x4.shared.b16 {%0,%1,%2,%3}, [%4];"
                 : "=r"(r0), "=r"(r1), "=r"(r2), "=r"(r3) : "r"(a));
}
__device__ __forceinline__ void ldsm_x4t(uint32_t& r0, uint32_t& r1, uint32_t& r2, uint32_t& r3, uint32_t a) {
    asm volatile("ldmatrix.sync.aligned.m8n8.x4.trans.shared.b16 {%0,%1,%2,%3}, [%4];"
                 : "=r"(r0), "=r"(r1), "=r"(r2), "=r"(r3) : "r"(a));
}
__device__ __forceinline__ void mma16816(float* c, uint32_t a0, uint32_t a1, uint32_t a2, uint32_t a3,
                                         uint32_t b0, uint32_t b1) {
    asm volatile("mma.sync.aligned.m16n8k16.row.col.f32.f16.f16.f32 "
                 "{%0,%1,%2,%3}, {%4,%5,%6,%7}, {%8,%9}, {%0,%1,%2,%3};"
                 : "+f"(c[0]), "+f"(c[1]), "+f"(c[2]), "+f"(c[3])
                 : "r"(a0), "r"(a1), "r"(a2), "r"(a3), "r"(b0), "r"(b1));
}

__global__ __launch_bounds__(256, 2)
void sparse_attn_hmma8(const float* __restrict__ q,
                       const float* __restrict__ k,
                       const float* __restrict__ v,
                       float* __restrict__ out)
{
    __shared__ __align__(16) __half Qs[128 * LDH];   // 18432 B
    __shared__ __align__(16) __half Ks[BSZ * LDH];   //  9216 B
    __shared__ __align__(16) __half Vs[BSZ * LDH];   //  9216 B

    const int bx   = blockIdx.x;          // 128-row q group (2 q-blocks)
    const int h    = blockIdx.y;
    const int tid  = threadIdx.x;
    const int lane = tid & 31;
    const int w    = tid >> 5;            // warp 0..7 -> rows 16w..16w+15

    const int my_ib = 2 * bx + (w >> 2);  // q-block of this warp
    const int ibp   = 2 * bx + 1;
    const int nnz   = (ibp <= 8) ? (ibp + 1) : 10;

    const float qscale = 0.125f * 1.4426950408889634f;

    // ---- load + prescale 128-row Q tile (256 threads) ----
    {
        const float* qg = q + ((size_t)h * SEQ + (size_t)bx * 128) * DIM;
        #pragma unroll
        for (int j = 0; j < 8; ++j) {
            int i   = tid + 256 * j;
            int row = i >> 4;
            int c4  = (i & 15) << 2;
            float4 val = *(const float4*)(qg + row * DIM + c4);
            uint2 u;
            u.x = pkh2(val.x * qscale, val.y * qscale);
            u.y = pkh2(val.z * qscale, val.w * qscale);
            *(uint2*)&Qs[row * LDH + c4] = u;
        }
    }
    __syncthreads();

    const uint32_t qsb = (uint32_t)__cvta_generic_to_shared(Qs);
    const uint32_t ksb = (uint32_t)__cvta_generic_to_shared(Ks);
    const uint32_t vsb = (uint32_t)__cvta_generic_to_shared(Vs);

    // ---- persistent Q A-fragments (one m-tile per warp) ----
    uint32_t aq[4][4];
    {
        int r   = lane & 15;
        int chi = (lane >> 4) * 8;
        uint32_t base = qsb + (((16 * w + r) * LDH + chi) << 1);
        #pragma unroll
        for (int c = 0; c < 4; ++c)
            ldsm_x4(aq[c][0], aq[c][1], aq[c][2], aq[c][3], base + ((16 * c) << 1));
    }

    const int g8 = lane >> 3;
    const int r8 = lane & 7;

    float O[8][4];
    #pragma unroll
    for (int j = 0; j < 8; ++j)
        #pragma unroll
        for (int e = 0; e < 4; ++e) O[j][e] = 0.f;
    float ls0 = 0.f, ls1 = 0.f;

    const int rloc  = 16 * (w & 3) + (lane >> 2);   // block-local row of elems 0/1
    const int c0loc = 2 * (lane & 3);

    for (int t = 0; t < nnz; ++t) {
        const int jb = (ibp <= 8) ? t : ((t == 0) ? 0 : (ibp - 9 + t));
        const bool active = (jb == 0) || (jb >= my_ib - (LOCALW - 1) && jb <= my_ib);

        // ---- load K, V tiles (256 threads: 2 float4 each per tensor) ----
        const float* kg = k + ((size_t)h * SEQ + (size_t)jb * BSZ) * DIM;
        const float* vg = v + ((size_t)h * SEQ + (size_t)jb * BSZ) * DIM;
        #pragma unroll
        for (int j = 0; j < 4; ++j) {
            int i   = tid + 256 * j;
            int row = i >> 4;
            int c4  = (i & 15) << 2;
            float4 kv = *(const float4*)(kg + row * DIM + c4);
            uint2 uk;
            uk.x = pkh2(kv.x, kv.y);
            uk.y = pkh2(kv.z, kv.w);
            *(uint2*)&Ks[row * LDH + c4] = uk;
            float4 vv = *(const float4*)(vg + row * DIM + c4);
            uint2 uv;
            uv.x = pkh2(vv.x, vv.y);
            uv.y = pkh2(vv.z, vv.w);
            *(uint2*)&Vs[row * LDH + c4] = uv;
        }
        __syncthreads();

        if (active) {
            const bool diag = (jb == my_ib);
            uint32_t pa[4][4];

            // ---- S tile nj: MMA -> immediate exp/pack (S live = 4 regs) ----
            #pragma unroll
            for (int nj = 0; nj < 8; ++nj) {
                float S[4] = {0.f, 0.f, 0.f, 0.f};
                uint32_t a0 = ksb + (((8 * nj + r8) * LDH + 8 * (g8 & 1) + 16 * (g8 >> 1)) << 1);
                uint32_t b0, b1, b2, b3, b4, b5, b6, b7;
                ldsm_x4(b0, b1, b2, b3, a0);
                ldsm_x4(b4, b5, b6, b7, a0 + 64);
                mma16816(S, aq[0][0], aq[0][1], aq[0][2], aq[0][3], b0, b1);
                mma16816(S, aq[1][0], aq[1][1], aq[1][2], aq[1][3], b2, b3);
                mma16816(S, aq[2][0], aq[2][1], aq[2][2], aq[2][3], b4, b5);
                mma16816(S, aq[3][0], aq[3][1], aq[3][2], aq[3][3], b6, b7);

                if (diag) {
                    int cn = 8 * nj + c0loc;
                    if (cn     > rloc)     S[0] = -1e30f;
                    if (cn + 1 > rloc)     S[1] = -1e30f;
                    if (cn     > rloc + 8) S[2] = -1e30f;
                    if (cn + 1 > rloc + 8) S[3] = -1e30f;
                }

                float p0 = ex2f(S[0]);
                float p1 = ex2f(S[1]);
                float p2 = ex2f(S[2]);
                float p3 = ex2f(S[3]);
                ls0 += p0 + p1;
                ls1 += p2 + p3;
                // pa[kchunk = nj>>1]; nj even -> regs 0/1 (k low), odd -> 2/3 (k high)
                int c  = nj >> 1;
                int hi = (nj & 1) << 1;
                pa[c][hi]     = pkh2(p0, p1);
                pa[c][hi + 1] = pkh2(p2, p3);
            }

            // ---- O += P @ V ----
            #pragma unroll
            for (int nj = 0; nj < 8; ++nj) {
                uint32_t v0 = vsb + (((8 * g8 + r8) * LDH + 8 * nj) << 1);
                uint32_t v1 = vsb + (((32 + 8 * g8 + r8) * LDH + 8 * nj) << 1);
                uint32_t c0, c1, c2, c3, c4, c5, c6, c7;
                ldsm_x4t(c0, c1, c2, c3, v0);
                ldsm_x4t(c4, c5, c6, c7, v1);
                mma16816(O[nj], pa[0][0], pa[0][1], pa[0][2], pa[0][3], c0, c1);
                mma16816(O[nj], pa[1][0], pa[1][1], pa[1][2], pa[1][3], c2, c3);
                mma16816(O[nj], pa[2][0], pa[2][1], pa[2][2], pa[2][3], c4, c5);
                mma16816(O[nj], pa[3][0], pa[3][1], pa[3][2], pa[3][3], c6, c7);
            }
        }
        __syncthreads();
    }

    // ---- epilogue: normalize + store ----
    float s0 = ls0 + __shfl_xor_sync(0xffffffffu, ls0, 1);
    s0 += __shfl_xor_sync(0xffffffffu, s0, 2);
    float s1 = ls1 + __shfl_xor_sync(0xffffffffu, ls1, 1);
    s1 += __shfl_xor_sync(0xffffffffu, s1, 2);
    float inv0 = 1.0f / s0;
    float inv1 = 1.0f / s1;

    float* og = out + ((size_t)h * SEQ + (size_t)bx * 128) * DIM;
    const int gr = 16 * w + (lane >> 2);
    #pragma unroll
    for (int nj = 0; nj < 8; ++nj) {
        int cn = 8 * nj + c0loc;
        float2 o0 = make_float2(O[nj][0] * inv0, O[nj][1] * inv0);
        float2 o1 = make_float2(O[nj][2] * inv1, O[nj][3] * inv1);
        *(float2*)(og + (size_t)gr * DIM + cn)       = o0;
        *(float2*)(og + (size_t)(gr + 8) * DIM + cn) = o1;
    }
}

extern "C" void kernel_launch(void* const* d_in, const int* in_sizes, int n_in,
                              void* d_out, int out_size)
{
    const float* q = (const float*)d_in[0];
    const float* k = (const float*)d_in[1];
    const float* v = (const float*)d_in[2];
    float* out = (float*)d_out;

    dim3 grid(NBLK / 2, HEADS);
    sparse_attn_hmma8<<<grid, 256>>>(q, k, v, out);
}